// round 4
// baseline (speedup 1.0000x reference)
#include <cuda_runtime.h>
#include <math.h>

#define BB 8
#define HH 128
#define WW 128
#define HW (HH*WW)

// ---------------- scratch (device globals; no runtime allocation) ----------------
__device__ float g_x1[BB*128*HW];     // conv1 out / fus conv out (64MB)
__device__ float g_x2[BB*64*HW];      // conv2 out / ce (32MB)
__device__ float g_de[BB*64*HW];      // de (32MB)
__device__ float g_cv[(size_t)BB*81*HW]; // cost volume (40.5MB)
__device__ float g_pred[BB*3*HW];
__device__ float g_valid[BB*HW];
__device__ float g_mean[5*BB*32];
__device__ float g_rstd[5*BB*32];
__device__ float g_veff[128];

// ---------------- 3x3 conv, pad=1, tiled ----------------
// Input channels split in half across two pointers (handles concat inputs and
// plain buffers uniformly). 16x16 spatial tile, COUT_PB outputs per block,
// 128 threads, each thread computes 2 horizontal pixels.
template<int CIN, int COUT_PB>
__launch_bounds__(128)
__global__ void conv3x3_k(const float* __restrict__ in0, const float* __restrict__ in1,
                          long bs0, long bs1,
                          const float* __restrict__ wgt,
                          float* __restrict__ out, int cout_total)
{
    constexpr int CT = 16;
    constexpr int HALF = CIN/2;
    __shared__ float s_in[CT*18*20];
    __shared__ float s_w[COUT_PB*CT*9];

    int tid = threadIdx.x;
    int tileIdx = blockIdx.x;
    int tx0 = (tileIdx & 7) * 16, ty0 = (tileIdx >> 3) * 16;
    int b = blockIdx.y;
    int co0 = blockIdx.z * COUT_PB;
    int tx = tid & 7, ty = tid >> 3;   // 8 pixel-pairs x 16 rows

    float acc[2*COUT_PB];
    #pragma unroll
    for (int i = 0; i < 2*COUT_PB; i++) acc[i] = 0.f;

    for (int c0 = 0; c0 < CIN; c0 += CT) {
        const float* inp = (c0 < HALF) ? (in0 + (long)b*bs0 + (long)c0*HW)
                                       : (in1 + (long)b*bs1 + (long)(c0-HALF)*HW);
        __syncthreads();
        // load 16ch x 18x18 input window (zero-padded)
        for (int i = tid; i < CT*18*18; i += 128) {
            int ci = i / 324; int r = i % 324; int y = r / 18, x = r % 18;
            int gy = ty0 + y - 1, gx = tx0 + x - 1;
            float v = 0.f;
            if ((unsigned)gy < 128u && (unsigned)gx < 128u)
                v = inp[ci*HW + gy*WW + gx];
            s_in[(ci*18 + y)*20 + x] = v;
        }
        // load weights chunk
        for (int i = tid; i < COUT_PB*CT*9; i += 128) {
            int co = i / (CT*9); int r = i % (CT*9);
            s_w[i] = wgt[(long)(co0+co)*CIN*9 + (long)c0*9 + r];
        }
        __syncthreads();

        #pragma unroll 1
        for (int ci = 0; ci < CT; ci++) {
            float v[12];
            #pragma unroll
            for (int r = 0; r < 3; r++)
                #pragma unroll
                for (int c = 0; c < 4; c++)
                    v[r*4+c] = s_in[(ci*18 + ty + r)*20 + 2*tx + c];
            #pragma unroll
            for (int co = 0; co < COUT_PB; co++) {
                const float* wp = &s_w[(co*CT + ci)*9];
                float a0 = acc[2*co], a1 = acc[2*co+1];
                #pragma unroll
                for (int r = 0; r < 3; r++) {
                    #pragma unroll
                    for (int k = 0; k < 3; k++) {
                        float wv = wp[r*3+k];
                        a0 = fmaf(wv, v[r*4+k],   a0);
                        a1 = fmaf(wv, v[r*4+k+1], a1);
                    }
                }
                acc[2*co] = a0; acc[2*co+1] = a1;
            }
        }
    }
    int gy = ty0 + ty, gx = tx0 + 2*tx;
    #pragma unroll
    for (int co = 0; co < COUT_PB; co++) {
        float2 val = make_float2(acc[2*co], acc[2*co+1]);
        *(float2*)&out[(((long)b*cout_total + co0+co)*HH + gy)*WW + gx] = val;
    }
}

// ---------------- GroupNorm statistics: one block per (group, batch) ----------------
__global__ void gn_stats_k(const float* __restrict__ x, float* __restrict__ mean,
                           float* __restrict__ rstd, int cpg)
{
    int g = blockIdx.x, b = blockIdx.y;
    int n = cpg * HW;
    const float* p = x + (size_t)(b*32 + g) * n;
    float s = 0.f, s2 = 0.f;
    for (int i = threadIdx.x*4; i < n; i += blockDim.x*4) {
        float4 v = *(const float4*)(p + i);
        s  += v.x + v.y + v.z + v.w;
        s2 += v.x*v.x + v.y*v.y + v.z*v.z + v.w*v.w;
    }
    __shared__ float sh[2][32];
    int lane = threadIdx.x & 31, wid = threadIdx.x >> 5;
    #pragma unroll
    for (int o = 16; o; o >>= 1) { s += __shfl_down_sync(~0u, s, o); s2 += __shfl_down_sync(~0u, s2, o); }
    if (lane == 0) { sh[0][wid] = s; sh[1][wid] = s2; }
    __syncthreads();
    if (wid == 0) {
        int nw = blockDim.x >> 5;
        s  = (lane < nw) ? sh[0][lane] : 0.f;
        s2 = (lane < nw) ? sh[1][lane] : 0.f;
        #pragma unroll
        for (int o = 16; o; o >>= 1) { s += __shfl_down_sync(~0u, s, o); s2 += __shfl_down_sync(~0u, s2, o); }
        if (lane == 0) {
            float m = s / n;
            float var = s2 / n - m*m;
            mean[b*32+g] = m;
            rstd[b*32+g] = rsqrtf(var + 1e-5f);
        }
    }
}

// ---------------- elementwise normalize + activation (ACT 0=silu, 1=relu), in place ----------------
template<int ACT>
__global__ void norm_act_k(float* __restrict__ x, const float* __restrict__ gamma,
                           const float* __restrict__ beta, const float* __restrict__ mean,
                           const float* __restrict__ rstd, int C, int cpg)
{
    size_t i4 = (size_t)blockIdx.x*blockDim.x + threadIdx.x;
    size_t e = i4 * 4;
    size_t total = (size_t)BB * C * HW;
    if (e >= total) return;
    int c = (int)((e / HW) % C);
    int b = (int)(e / ((size_t)HW * C));
    int g = c / cpg;
    float m = mean[b*32+g], rs = rstd[b*32+g];
    float ga = gamma[c] * rs;
    float be = beta[c] - m * ga;
    float4 v = *(float4*)(x + e);
    float o[4] = {v.x, v.y, v.z, v.w};
    #pragma unroll
    for (int k = 0; k < 4; k++) {
        float y = o[k]*ga + be;
        if (ACT == 0) y = y / (1.f + expf(-y));  // silu
        else          y = fmaxf(y, 0.f);          // relu
        o[k] = y;
    }
    *(float4*)(x + e) = make_float4(o[0], o[1], o[2], o[3]);
}

// ---------------- flow + validity from pred ----------------
__global__ void flowval_k(const float* __restrict__ pred, const float* __restrict__ bias3,
                          float* __restrict__ out_flow, float* __restrict__ valid)
{
    int i = blockIdx.x*blockDim.x + threadIdx.x;
    if (i >= BB*HW) return;
    int b = i / HW, hw = i % HW;
    out_flow[(b*2+0)*HW + hw] = pred[(b*3+0)*HW + hw] + bias3[0];
    out_flow[(b*2+1)*HW + hw] = pred[(b*3+1)*HW + hw] + bias3[1];
    float z = pred[(b*3+2)*HW + hw] + bias3[2];
    valid[i] = 1.f / (1.f + expf(-z));
}

// ---------------- bilinear warp * validity ----------------
__global__ void warp_k(const float* __restrict__ feat2, const float* __restrict__ flow,
                       const float* __restrict__ valid, float* __restrict__ aligned)
{
    int i = blockIdx.x*blockDim.x + threadIdx.x;
    if (i >= BB*HW) return;
    int b = i / HW, hw = i % HW;
    int h = hw / WW, w = hw % WW;
    float px = (float)w + flow[(b*2+0)*HW + hw];
    float py = (float)h + flow[(b*2+1)*HW + hw];
    float x0f = floorf(px), y0f = floorf(py);
    float wx = px - x0f, wy = py - y0f;
    int x0 = (int)x0f, y0 = (int)y0f;
    int x1 = x0 + 1, y1 = y0 + 1;
    float m00 = (x0 >= 0 && x0 < WW && y0 >= 0 && y0 < HH) ? 1.f : 0.f;
    float m10 = (x1 >= 0 && x1 < WW && y0 >= 0 && y0 < HH) ? 1.f : 0.f;
    float m01 = (x0 >= 0 && x0 < WW && y1 >= 0 && y1 < HH) ? 1.f : 0.f;
    float m11 = (x1 >= 0 && x1 < WW && y1 >= 0 && y1 < HH) ? 1.f : 0.f;
    int xc0 = min(max(x0,0),WW-1), xc1 = min(max(x1,0),WW-1);
    int yc0 = min(max(y0,0),HH-1), yc1 = min(max(y1,0),HH-1);
    float w00 = (1.f-wx)*(1.f-wy)*m00, w10 = wx*(1.f-wy)*m10;
    float w01 = (1.f-wx)*wy*m01,       w11 = wx*wy*m11;
    float vd = valid[i];
    int o00 = yc0*WW+xc0, o10 = yc0*WW+xc1, o01 = yc1*WW+xc0, o11 = yc1*WW+xc1;
    const float* base = feat2 + (size_t)b*128*HW;
    float* obase = aligned + (size_t)b*128*HW + hw;
    #pragma unroll 4
    for (int c = 0; c < 128; c++) {
        const float* img = base + (size_t)c*HW;
        float s = img[o00]*w00 + img[o10]*w10 + img[o01]*w01 + img[o11]*w11;
        obase[(size_t)c*HW] = s * vd;
    }
}

// ---------------- cost volume: 81 displacements, mean over 128 channels ----------------
__launch_bounds__(256)
__global__ void costvol_k(const float* __restrict__ f1, const float* __restrict__ al,
                          float* __restrict__ cv)
{
    __shared__ float s[8*24*25];
    int tid = threadIdx.x;
    int tileIdx = blockIdx.x;
    int tx0 = (tileIdx & 7) * 16, ty0 = (tileIdx >> 3) * 16;
    int b = blockIdx.y;
    int tx = tid & 15, ty = tid >> 4;
    float acc[81];
    #pragma unroll
    for (int d = 0; d < 81; d++) acc[d] = 0.f;

    for (int c0 = 0; c0 < 128; c0 += 8) {
        __syncthreads();
        for (int i = tid; i < 8*24*24; i += 256) {
            int ci = i / 576, r = i % 576, y = r / 24, x = r % 24;
            int gy = ty0 + y - 4, gx = tx0 + x - 4;
            float v = 0.f;
            if ((unsigned)gy < 128u && (unsigned)gx < 128u)
                v = al[(size_t)(b*128 + c0 + ci)*HW + gy*WW + gx];
            s[(ci*24 + y)*25 + x] = v;
        }
        __syncthreads();
        #pragma unroll 1
        for (int ci = 0; ci < 8; ci++) {
            float f = f1[(size_t)(b*128 + c0 + ci)*HW + (ty0+ty)*WW + tx0+tx];
            #pragma unroll
            for (int dy = 0; dy < 9; dy++)
                #pragma unroll
                for (int dx = 0; dx < 9; dx++)
                    acc[dy*9+dx] = fmaf(f, s[(ci*24 + ty + dy)*25 + tx + dx], acc[dy*9+dx]);
        }
    }
    const float inv = 1.f / 128.f;
    int off = (ty0+ty)*WW + tx0+tx;
    #pragma unroll 1
    for (int d = 0; d < 81; d++)
        cv[(size_t)(b*81 + d)*HW + off] = acc[d] * inv;
}

// ---------------- 1x1 conv (MODE 0: plain read; MODE 1: |inA - inB| on the fly) ----------------
template<int CIN, int COUT, int MODE>
__launch_bounds__(128)
__global__ void conv1x1_k(const float* __restrict__ inA, const float* __restrict__ inB,
                          const float* __restrict__ wgt, float* __restrict__ out)
{
    __shared__ float s_w[COUT*CIN];
    for (int i = threadIdx.x; i < COUT*CIN; i += 128) s_w[i] = wgt[i];
    __syncthreads();
    int p = blockIdx.x*128 + threadIdx.x;
    int b = p / HW, hw = p % HW;
    float acc[COUT];
    #pragma unroll
    for (int co = 0; co < COUT; co++) acc[co] = 0.f;
    #pragma unroll 1
    for (int ci = 0; ci < CIN; ci++) {
        float v;
        if (MODE == 1) {
            size_t idx = (size_t)(b*128 + ci)*HW + hw;
            v = fabsf(inA[idx] - inB[idx]);
        } else {
            v = inA[(size_t)(b*CIN + ci)*HW + hw];
        }
        #pragma unroll
        for (int co = 0; co < COUT; co++)
            acc[co] = fmaf(s_w[co*CIN + ci], v, acc[co]);
    }
    #pragma unroll 1
    for (int co = 0; co < COUT; co++)
        out[(size_t)(b*COUT + co)*HW + hw] = acc[co];
}

// ---------------- effective lam weight: veff[ci] = sum_co lam_w[co] * fus_w2[co][ci] ----------------
__global__ void lam_eff_k(const float* __restrict__ lam_w, const float* __restrict__ fus_w2,
                          float* __restrict__ veff)
{
    int ci = threadIdx.x;
    float a = 0.f;
    for (int co = 0; co < 128; co++)
        a = fmaf(lam_w[co], fus_w2[co*128 + ci], a);
    veff[ci] = a;
}

// ---------------- final: GN(fus)->relu -> dot(veff) -> sigmoid ----------------
__global__ void lam_final_k(const float* __restrict__ fbuf, const float* __restrict__ gamma,
                            const float* __restrict__ beta, const float* __restrict__ mean,
                            const float* __restrict__ rstd, const float* __restrict__ veff,
                            const float* __restrict__ lam_b, float* __restrict__ out_lam)
{
    __shared__ float sg[128], sb[128], sv[128];
    for (int i = threadIdx.x; i < 128; i += blockDim.x) {
        sg[i] = gamma[i]; sb[i] = beta[i]; sv[i] = veff[i];
    }
    __syncthreads();
    int p = blockIdx.x*blockDim.x + threadIdx.x;
    if (p >= BB*HW) return;
    int b = p / HW, hw = p % HW;
    float a = lam_b[0];
    const float* fb = fbuf + (size_t)b*128*HW + hw;
    const float* mp = mean + b*32;
    const float* rp = rstd + b*32;
    #pragma unroll 4
    for (int ci = 0; ci < 128; ci++) {
        float x = fb[(size_t)ci*HW];
        int g = ci >> 2;
        float y = (x - mp[g]) * rp[g] * sg[ci] + sb[ci];
        a = fmaf(fmaxf(y, 0.f), sv[ci], a);
    }
    out_lam[p] = 1.f / (1.f + expf(-a));
}

// ---------------- launch ----------------
extern "C" void kernel_launch(void* const* d_in, const int* in_sizes, int n_in,
                              void* d_out, int out_size)
{
    const float* feat1     = (const float*)d_in[0];
    const float* feat2     = (const float*)d_in[1];
    const float* off_w1    = (const float*)d_in[2];
    const float* off_g1    = (const float*)d_in[3];
    const float* off_b1    = (const float*)d_in[4];
    const float* off_w2    = (const float*)d_in[5];
    const float* off_g2    = (const float*)d_in[6];
    const float* off_b2    = (const float*)d_in[7];
    const float* off_w3    = (const float*)d_in[8];
    const float* off_bias3 = (const float*)d_in[9];
    const float* corr_w    = (const float*)d_in[10];
    const float* corr_g    = (const float*)d_in[11];
    const float* corr_b    = (const float*)d_in[12];
    const float* diff_w    = (const float*)d_in[13];
    const float* diff_g    = (const float*)d_in[14];
    const float* diff_b    = (const float*)d_in[15];
    const float* fus_w1    = (const float*)d_in[16];
    const float* fus_g1    = (const float*)d_in[17];
    const float* fus_b1    = (const float*)d_in[18];
    const float* fus_w2    = (const float*)d_in[19];
    const float* lam_w     = (const float*)d_in[20];
    const float* lam_b     = (const float*)d_in[21];

    float *x1, *x2, *de, *cv, *pred, *valid, *mean, *rstd, *veff;
    cudaGetSymbolAddress((void**)&x1,    g_x1);
    cudaGetSymbolAddress((void**)&x2,    g_x2);
    cudaGetSymbolAddress((void**)&de,    g_de);
    cudaGetSymbolAddress((void**)&cv,    g_cv);
    cudaGetSymbolAddress((void**)&pred,  g_pred);
    cudaGetSymbolAddress((void**)&valid, g_valid);
    cudaGetSymbolAddress((void**)&mean,  g_mean);
    cudaGetSymbolAddress((void**)&rstd,  g_rstd);
    cudaGetSymbolAddress((void**)&veff,  g_veff);

    float* out_aligned = (float*)d_out;
    float* out_flow    = out_aligned + (size_t)BB*128*HW;
    float* out_lam     = out_flow    + (size_t)BB*2*HW;

    float* mean0 = mean;          float* rstd0 = rstd;
    float* mean1 = mean + 256;    float* rstd1 = rstd + 256;
    float* mean2 = mean + 512;    float* rstd2 = rstd + 512;
    float* mean3 = mean + 768;    float* rstd3 = rstd + 768;
    float* mean4 = mean + 1024;   float* rstd4 = rstd + 1024;

    const long BS128 = (long)128*HW;
    const long BS64  = (long)64*HW;

    // offset head: conv1 (concat feat1|feat2) -> GN -> silu
    conv3x3_k<256,32><<<dim3(64,BB,4),128>>>(feat1, feat2, BS128, BS128, off_w1, x1, 128);
    gn_stats_k<<<dim3(32,BB),256>>>(x1, mean0, rstd0, 4);
    norm_act_k<0><<<(BB*128*HW/4+255)/256,256>>>(x1, off_g1, off_b1, mean0, rstd0, 128, 4);

    // conv2 -> GN -> silu
    conv3x3_k<128,32><<<dim3(64,BB,2),128>>>(x1, x1 + 64*HW, BS128, BS128, off_w2, x2, 64);
    gn_stats_k<<<dim3(32,BB),256>>>(x2, mean1, rstd1, 2);
    norm_act_k<0><<<(BB*64*HW/4+255)/256,256>>>(x2, off_g2, off_b2, mean1, rstd1, 64, 2);

    // conv3 -> pred; flow + validity
    conv3x3_k<64,3><<<dim3(64,BB,1),128>>>(x2, x2 + 32*HW, BS64, BS64, off_w3, pred, 3);
    flowval_k<<<(BB*HW+255)/256,256>>>(pred, off_bias3, out_flow, valid);

    // bilinear warp * validity -> aligned (directly into d_out)
    warp_k<<<(BB*HW+255)/256,256>>>(feat2, out_flow, valid, out_aligned);

    // cost volume
    costvol_k<<<dim3(64,BB),256>>>(feat1, out_aligned, cv);

    // corr branch: 1x1(81->64) -> GN -> relu   (ce reuses x2)
    conv1x1_k<81,64,0><<<BB*HW/128,128>>>(cv, nullptr, corr_w, x2);
    gn_stats_k<<<dim3(32,BB),256>>>(x2, mean2, rstd2, 2);
    norm_act_k<1><<<(BB*64*HW/4+255)/256,256>>>(x2, corr_g, corr_b, mean2, rstd2, 64, 2);

    // diff branch: |feat1-aligned| fused into 1x1(128->64) -> GN -> relu
    conv1x1_k<128,64,1><<<BB*HW/128,128>>>(feat1, out_aligned, diff_w, de);
    gn_stats_k<<<dim3(32,BB),256>>>(de, mean3, rstd3, 2);
    norm_act_k<1><<<(BB*64*HW/4+255)/256,256>>>(de, diff_g, diff_b, mean3, rstd3, 64, 2);

    // fusion conv3x3 (concat ce|de) -> GN stats (norm fused into final)
    conv3x3_k<128,32><<<dim3(64,BB,4),128>>>(x2, de, BS64, BS64, fus_w1, x1, 128);
    gn_stats_k<<<dim3(32,BB),256>>>(x1, mean4, rstd4, 4);

    // lam: veff = lam_w @ fus_w2, then per-pixel dot + sigmoid
    lam_eff_k<<<1,128>>>(lam_w, fus_w2, veff);
    lam_final_k<<<(BB*HW+255)/256,256>>>(x1, fus_g1, fus_b1, mean4, rstd4, veff, lam_b, out_lam);
}